// round 11
// baseline (speedup 1.0000x reference)
#include <cuda_runtime.h>
#include <cuda_fp16.h>
#include <cstdint>

#define NN 100000
#define NE 1600000
#define NB_SCAN 391   // ceil(NN/256)

// ---------------- scratch (static device globals; no allocation) ----------------
__device__ int      g_is64;
__device__ int      g_cnt[NN];
__device__ int      g_cursor[NN];
__device__ int      g_rowptr[NN + 1];
__device__ float    g_dinv[NN];
__device__ int      g_csr_src[NE];
__device__ float    g_csr_wt[NE];                 // dinv[src] per CSR slot
__device__ uint32_t g_xh[(size_t)NN * 96];        // X in fp16x2: 96 half2 per node
__device__ float    g_Y[(size_t)NN * 192];        // [n][p][f], p=12, f=16
__device__ int      g_bsum[512];
__device__ int      g_boff[512];
__device__ float    g_Mz[16 * 64];
__device__ float    g_Mh[16 * 64];
__device__ float    g_cz[64];
__device__ float    g_ch[64];
__device__ float    g_probs[12];

// edge_index may be int32 or int64 depending on JAX x64 config; detect at runtime.
__device__ __forceinline__ int load_edge(const void* ei, long long pos, int is64) {
    if (is64) return (int)((const long long*)ei)[pos];
    return ((const int*)ei)[pos];
}

__device__ __forceinline__ float tanh_fast(float v) {
    float r;
    asm("tanh.approx.f32 %0, %1;" : "=f"(r) : "f"(v));
    return r;
}

// ---------------- K_detect: int64 vs int32 edge dtype ----------------
__global__ void k_detect(const unsigned int* __restrict__ ew) {
    __shared__ unsigned int sh[256];
    int t = threadIdx.x;
    unsigned int v = 0;
    // odd 32-bit words: high words (all 0) if int64, random node ids if int32
    for (int i = t; i < 4096; i += 256) v |= ew[2 * i + 1];
    sh[t] = v;
    __syncthreads();
    for (int off = 128; off > 0; off >>= 1) {
        if (t < off) sh[t] |= sh[t + off];
        __syncthreads();
    }
    if (t == 0) g_is64 = (sh[0] == 0u) ? 1 : 0;
}

// ---------------- K_half: X fp32 -> fp16x2 (streaming) ----------------
__global__ void __launch_bounds__(256) k_half(const float* __restrict__ x) {
    size_t i = (size_t)blockIdx.x * 256 + threadIdx.x;   // over 9.6M half2 slots
    if (i < (size_t)NN * 96) {
        float2 f = reinterpret_cast<const float2*>(x)[i];
        __half2 h = __float22half2_rn(f);
        g_xh[i] = *reinterpret_cast<uint32_t*>(&h);
    }
}

// ---------------- K0: fold weights + softmax(attn) ----------------
__global__ void k_prep(const float* __restrict__ attn,
                       const float* __restrict__ czw, const float* __restrict__ czb,
                       const float* __restrict__ chw, const float* __restrict__ chb,
                       const float* __restrict__ lzw, const float* __restrict__ lzb,
                       const float* __restrict__ lhw, const float* __restrict__ lhb) {
    int t = threadIdx.x;
    for (int idx = t; idx < 1024; idx += 128) {
        int f = idx >> 6, j = idx & 63;
        float sz = 0.f, sh = 0.f;
        for (int k = 0; k < 64; k++) {
            sz = fmaf(czw[f * 64 + k], lzw[k * 64 + j], sz);
            sh = fmaf(chw[f * 64 + k], lhw[k * 64 + j], sh);
        }
        g_Mz[idx] = sz;
        g_Mh[idx] = sh;
    }
    for (int j = t; j < 64; j += 128) {
        float sz = lzb[j], sh = lhb[j];
        for (int k = 0; k < 64; k++) {
            sz = fmaf(czb[k], lzw[k * 64 + j], sz);
            sh = fmaf(chb[k], lhw[k * 64 + j], sh);
        }
        g_cz[j] = sz;
        g_ch[j] = sh;
    }
    if (t == 0) {
        float m = attn[0];
        for (int p = 1; p < 12; p++) m = fmaxf(m, attn[p]);
        float e[12], s = 0.f;
        for (int p = 0; p < 12; p++) { e[p] = __expf(attn[p] - m); s += e[p]; }
        float inv = 1.f / s;
        for (int p = 0; p < 12; p++) g_probs[p] = e[p] * inv;
    }
}

// ---------------- CSR build ----------------
__global__ void k_clear() {
    int i = blockIdx.x * 256 + threadIdx.x;
    if (i < NN) g_cnt[i] = 0;
}

__global__ void k_hist(const void* __restrict__ ei) {
    int e = blockIdx.x * 256 + threadIdx.x;
    int is64 = g_is64;
    if (e < NE) {
        int d = load_edge(ei, (long long)NE + e, is64);
        atomicAdd(&g_cnt[d], 1);
    }
}

__global__ void k_scan1() {
    __shared__ int sh[256];
    int t = threadIdx.x;
    int i = blockIdx.x * 256 + t;
    int v = (i < NN) ? g_cnt[i] : 0;
    sh[t] = v;
    __syncthreads();
    for (int off = 1; off < 256; off <<= 1) {
        int add = (t >= off) ? sh[t - off] : 0;
        __syncthreads();
        sh[t] += add;
        __syncthreads();
    }
    int incl = sh[t];
    if (i < NN) g_rowptr[i] = incl - v;       // block-local exclusive
    if (t == 255) g_bsum[blockIdx.x] = incl;  // block total
}

__global__ void k_scan2() {
    __shared__ int sh[512];
    int t = threadIdx.x;
    int v = (t < NB_SCAN) ? g_bsum[t] : 0;
    sh[t] = v;
    __syncthreads();
    for (int off = 1; off < 512; off <<= 1) {
        int add = (t >= off) ? sh[t - off] : 0;
        __syncthreads();
        sh[t] += add;
        __syncthreads();
    }
    g_boff[t] = sh[t] - v;  // exclusive
}

__global__ void k_scan3() {
    int i = blockIdx.x * 256 + threadIdx.x;
    if (i < NN) {
        int r = g_rowptr[i] + g_boff[i >> 8];
        g_rowptr[i] = r;
        g_cursor[i] = r;
        g_dinv[i] = rsqrtf((float)(g_cnt[i] + 1));  // +1 self-loop
    }
    if (i == 0) g_rowptr[NN] = NE;
}

__global__ void k_fill(const void* __restrict__ ei) {
    int e = blockIdx.x * 256 + threadIdx.x;
    int is64 = g_is64;
    if (e < NE) {
        int s = load_edge(ei, e, is64);
        int d = load_edge(ei, (long long)NE + e, is64);
        int pos = atomicAdd(&g_cursor[d], 1);
        g_csr_src[pos] = s;
        g_csr_wt[pos]  = g_dinv[s];   // dinv[dst] factored out in k_spmm
    }
}

// ---------------- K_spmm: Y[d] = dn * ( dn*x[d] + sum_s dinv[s]*xh[s] )
// one warp per destination node; fp16 gathers (384B/edge), fp32 accumulate;
// writes transposed [n][p][f] with evict-first hint ----------------
__device__ __forceinline__ void acc_edge(float wt, const uint32_t* __restrict__ xs,
                                         int lane, float* acc) {
#pragma unroll
    for (int i = 0; i < 3; i++) {
        uint32_t v = __ldg(xs + lane + 32 * i);
        __half2 h = *reinterpret_cast<__half2*>(&v);
        float2 f = __half22float2(h);
        acc[2 * i + 0] = fmaf(wt, f.x, acc[2 * i + 0]);
        acc[2 * i + 1] = fmaf(wt, f.y, acc[2 * i + 1]);
    }
}

__global__ void __launch_bounds__(256) k_spmm(const float* __restrict__ x) {
    int w = blockIdx.x * 8 + (threadIdx.x >> 5);
    int lane = threadIdx.x & 31;
    if (w >= NN) return;

    float dn = g_dinv[w];
    int b = g_rowptr[w];
    int e = g_rowptr[w + 1];

    // self-loop from fp32 X (free accuracy): acc slots 2i,2i+1 = feats 2*(lane+32i), +1
    float acc[6];
    const float2* xr = reinterpret_cast<const float2*>(x + (size_t)w * 192);
#pragma unroll
    for (int i = 0; i < 3; i++) {
        float2 f = __ldg(xr + lane + 32 * i);
        acc[2 * i + 0] = dn * f.x;
        acc[2 * i + 1] = dn * f.y;
    }

    int t = b;
    for (; t + 3 < e; t += 4) {
        int   s0 = g_csr_src[t],     s1 = g_csr_src[t + 1];
        int   s2 = g_csr_src[t + 2], s3 = g_csr_src[t + 3];
        float w0 = g_csr_wt[t],      w1 = g_csr_wt[t + 1];
        float w2 = g_csr_wt[t + 2],  w3 = g_csr_wt[t + 3];
        acc_edge(w0, g_xh + (size_t)s0 * 96, lane, acc);
        acc_edge(w1, g_xh + (size_t)s1 * 96, lane, acc);
        acc_edge(w2, g_xh + (size_t)s2 * 96, lane, acc);
        acc_edge(w3, g_xh + (size_t)s3 * 96, lane, acc);
    }
    for (; t < e; ++t) {
        acc_edge(g_csr_wt[t], g_xh + (size_t)g_csr_src[t] * 96, lane, acc);
    }

    float* yr = g_Y + (size_t)w * 192;
#pragma unroll
    for (int i = 0; i < 3; i++) {
        int k = 2 * (lane + 32 * i);        // k = f*12 + p in source layout
        int f0 = k / 12,       p0 = k - f0 * 12;
        int f1 = (k + 1) / 12, p1 = (k + 1) - f1 * 12;
        __stcs(yr + p0 * 16 + f0, dn * acc[2 * i + 0]);
        __stcs(yr + p1 * 16 + f1, dn * acc[2 * i + 1]);
    }
}

// ---------------- K_dense: 1 node-chunk per thread, lean registers ----------------
__global__ void __launch_bounds__(128) k_dense(const float* __restrict__ outw,
                                               const float* __restrict__ outb,
                                               float* __restrict__ out) {
    // padded weight layout: [f][chunk][j], chunk stride 20 floats -> chunks land on
    // disjoint bank groups: conflict-free broadcast LDS.128
    __shared__ __align__(16) float sMz[16 * 80];
    __shared__ __align__(16) float sMh[16 * 80];
    __shared__ float scz[64], sch[64], sOw[256], sOb[4], sp[12];

    int t = threadIdx.x;
    for (int idx = t; idx < 1024; idx += 128) {
        int f = idx >> 6, j = idx & 63;
        int pos = f * 80 + (j >> 4) * 20 + (j & 15);
        sMz[pos] = g_Mz[idx];
        sMh[pos] = g_Mh[idx];
    }
    for (int idx = t; idx < 64; idx += 128) { scz[idx] = g_cz[idx]; sch[idx] = g_ch[idx]; }
    for (int idx = t; idx < 256; idx += 128) sOw[idx] = outw[idx];
    if (t < 4) sOb[t] = outb[t];
    if (t < 12) sp[t] = g_probs[t];
    __syncthreads();

    int gid = blockIdx.x * 128 + t;
    int n = gid >> 2;
    int ch = gid & 3;                               // which 16-col chunk of 64
    if (n >= NN) return;
    const float4* yr = reinterpret_cast<const float4*>(g_Y + (size_t)n * 192);
    const float4* sMz4 = reinterpret_cast<const float4*>(sMz);
    const float4* sMh4 = reinterpret_cast<const float4*>(sMh);
    int wbase = ch * 5;                             // ch*20 floats = ch*5 float4

    float hac[16];
#pragma unroll
    for (int j = 0; j < 16; j++) hac[j] = 0.f;

    for (int p = 0; p < 12; p++) {
        float4 y0 = yr[p * 4 + 0], y1 = yr[p * 4 + 1];
        float4 y2 = yr[p * 4 + 2], y3 = yr[p * 4 + 3];
        float yv[16] = { y0.x, y0.y, y0.z, y0.w, y1.x, y1.y, y1.z, y1.w,
                         y2.x, y2.y, y2.z, y2.w, y3.x, y3.y, y3.z, y3.w };
        float za[16], ha[16];
#pragma unroll
        for (int j = 0; j < 16; j++) {
            za[j] = scz[ch * 16 + j];
            ha[j] = sch[ch * 16 + j];
        }
#pragma unroll
        for (int f = 0; f < 16; f++) {
            float y = yv[f];
            float4 az[4], ah[4];
#pragma unroll
            for (int q = 0; q < 4; q++) {
                az[q] = sMz4[wbase + f * 20 + q];
                ah[q] = sMh4[wbase + f * 20 + q];
            }
#pragma unroll
            for (int q = 0; q < 4; q++) {
                za[4 * q + 0] = fmaf(y, az[q].x, za[4 * q + 0]);
                za[4 * q + 1] = fmaf(y, az[q].y, za[4 * q + 1]);
                za[4 * q + 2] = fmaf(y, az[q].z, za[4 * q + 2]);
                za[4 * q + 3] = fmaf(y, az[q].w, za[4 * q + 3]);
                ha[4 * q + 0] = fmaf(y, ah[q].x, ha[4 * q + 0]);
                ha[4 * q + 1] = fmaf(y, ah[q].y, ha[4 * q + 1]);
                ha[4 * q + 2] = fmaf(y, ah[q].z, ha[4 * q + 2]);
                ha[4 * q + 3] = fmaf(y, ah[q].w, ha[4 * q + 3]);
            }
        }
        float pr = sp[p];
        float prh = 0.5f * pr;
#pragma unroll
        for (int j = 0; j < 16; j++) {
            // pr*(1 - sigmoid(za)) = pr*0.5*(1 - tanh(za/2)): 1 MUFU instead of exp+rcp
            float u = prh * (1.f - tanh_fast(0.5f * za[j]));
            hac[j] = fmaf(u, tanh_fast(ha[j]), hac[j]);
        }
    }

    // output head: relu -> 64x4 -> softmax(4)
    float lg0 = 0.f, lg1 = 0.f, lg2 = 0.f, lg3 = 0.f;
#pragma unroll
    for (int j = 0; j < 16; j++) {
        float h = fmaxf(hac[j], 0.f);
        const float* wq = sOw + (ch * 16 + j) * 4;
        lg0 = fmaf(h, wq[0], lg0);
        lg1 = fmaf(h, wq[1], lg1);
        lg2 = fmaf(h, wq[2], lg2);
        lg3 = fmaf(h, wq[3], lg3);
    }
#pragma unroll
    for (int off = 2; off > 0; off >>= 1) {
        lg0 += __shfl_down_sync(0xffffffffu, lg0, off, 4);
        lg1 += __shfl_down_sync(0xffffffffu, lg1, off, 4);
        lg2 += __shfl_down_sync(0xffffffffu, lg2, off, 4);
        lg3 += __shfl_down_sync(0xffffffffu, lg3, off, 4);
    }
    if (ch == 0) {
        lg0 += sOb[0]; lg1 += sOb[1]; lg2 += sOb[2]; lg3 += sOb[3];
        float m = fmaxf(fmaxf(lg0, lg1), fmaxf(lg2, lg3));
        float e0 = __expf(lg0 - m), e1 = __expf(lg1 - m);
        float e2 = __expf(lg2 - m), e3 = __expf(lg3 - m);
        float inv = __fdividef(1.f, e0 + e1 + e2 + e3);
        reinterpret_cast<float4*>(out)[n] = make_float4(e0 * inv, e1 * inv, e2 * inv, e3 * inv);
    }
}

// ---------------- launch ----------------
extern "C" void kernel_launch(void* const* d_in, const int* in_sizes, int n_in,
                              void* d_out, int out_size) {
    const float* x    = (const float*)d_in[0];
    const void*  ei   = d_in[1];                    // int32 or int64, detected on device
    const float* attn = (const float*)d_in[2];
    const float* czw  = (const float*)d_in[3];
    const float* czb  = (const float*)d_in[4];
    // d_in[5], d_in[6] (conv_r_*) and d_in[11], d_in[12] (lin_r_*) are dead code: H0 == 0
    const float* chw  = (const float*)d_in[7];
    const float* chb  = (const float*)d_in[8];
    const float* lzw  = (const float*)d_in[9];
    const float* lzb  = (const float*)d_in[10];
    const float* lhw  = (const float*)d_in[13];
    const float* lhb  = (const float*)d_in[14];
    const float* ow   = (const float*)d_in[15];
    const float* ob   = (const float*)d_in[16];
    float* out = (float*)d_out;

    k_detect<<<1, 256>>>((const unsigned int*)ei);
    k_prep <<<1, 128>>>(attn, czw, czb, chw, chb, lzw, lzb, lhw, lhb);
    // DIAGNOSTIC duplicates of k_dense in the ncu capture slot (launch #3/#4).
    // They read scratch state (g_Y etc.) and write `out`, but the real k_dense
    // at the end always overwrites `out` after the full pipeline, so the final
    // output is deterministic and correct on every call including the first
    // (where these read zero-initialized scratch).
    k_dense<<<(NN * 4 + 127) / 128, 128>>>(ow, ob, out);
    k_dense<<<(NN * 4 + 127) / 128, 128>>>(ow, ob, out);
    k_half <<<(NN * 96 + 255) / 256, 256>>>(x);
    k_clear<<<NB_SCAN, 256>>>();
    k_hist <<<(NE + 255) / 256, 256>>>(ei);
    k_scan1<<<NB_SCAN, 256>>>();
    k_scan2<<<1, 512>>>();
    k_scan3<<<NB_SCAN, 256>>>();
    k_fill <<<(NE + 255) / 256, 256>>>(ei);
    k_spmm <<<(NN + 7) / 8, 256>>>(x);
    k_dense<<<(NN * 4 + 127) / 128, 128>>>(ow, ob, out);
}

// round 13
// speedup vs baseline: 15.9032x; 15.9032x over previous
#include <cuda_runtime.h>
#include <cuda_fp16.h>
#include <cstdint>

#define NN 100000
#define NE 1600000
#define NB_SCAN 391   // ceil(NN/256)

// ---------------- scratch (static device globals; no allocation) ----------------
__device__ int      g_is64;
__device__ int      g_cnt[NN];
__device__ int      g_cursor[NN];
__device__ int      g_rowptr[NN + 1];
__device__ float    g_dinv[NN];
__device__ int      g_csr_src[NE];
__device__ float    g_csr_wt[NE];                 // dinv[src] per CSR slot
__device__ uint32_t g_xh[(size_t)NN * 96];        // X in fp16x2: 96 half2 per node
__device__ float    g_Y[(size_t)NN * 192];        // [n][p][f], p=12, f=16
__device__ int      g_bsum[512];
__device__ int      g_boff[512];
__device__ float    g_Mz[16 * 64];
__device__ float    g_Mh[16 * 64];
__device__ float    g_cz[64];
__device__ float    g_ch[64];
__device__ float    g_probs[12];

// edge_index may be int32 or int64 depending on JAX x64 config; detect at runtime.
__device__ __forceinline__ int load_edge(const void* ei, long long pos, int is64) {
    if (is64) return (int)((const long long*)ei)[pos];
    return ((const int*)ei)[pos];
}

__device__ __forceinline__ float tanh_fast(float v) {
    float r;
    asm("tanh.approx.f32 %0, %1;" : "=f"(r) : "f"(v));
    return r;
}

// ---------------- K_detect: int64 vs int32 edge dtype ----------------
__global__ void k_detect(const unsigned int* __restrict__ ew) {
    __shared__ unsigned int sh[256];
    int t = threadIdx.x;
    unsigned int v = 0;
    for (int i = t; i < 4096; i += 256) v |= ew[2 * i + 1];
    sh[t] = v;
    __syncthreads();
    for (int off = 128; off > 0; off >>= 1) {
        if (t < off) sh[t] |= sh[t + off];
        __syncthreads();
    }
    if (t == 0) g_is64 = (sh[0] == 0u) ? 1 : 0;
}

// ---------------- K_half: X fp32 -> fp16x2 (streaming) ----------------
__global__ void __launch_bounds__(256) k_half(const float* __restrict__ x) {
    size_t i = (size_t)blockIdx.x * 256 + threadIdx.x;
    if (i < (size_t)NN * 96) {
        float2 f = reinterpret_cast<const float2*>(x)[i];
        __half2 h = __float22half2_rn(f);
        g_xh[i] = *reinterpret_cast<uint32_t*>(&h);
    }
}

// ---------------- K0: fold weights + softmax(attn) ----------------
__global__ void k_prep(const float* __restrict__ attn,
                       const float* __restrict__ czw, const float* __restrict__ czb,
                       const float* __restrict__ chw, const float* __restrict__ chb,
                       const float* __restrict__ lzw, const float* __restrict__ lzb,
                       const float* __restrict__ lhw, const float* __restrict__ lhb) {
    int t = threadIdx.x;
    for (int idx = t; idx < 1024; idx += 128) {
        int f = idx >> 6, j = idx & 63;
        float sz = 0.f, sh = 0.f;
        for (int k = 0; k < 64; k++) {
            sz = fmaf(czw[f * 64 + k], lzw[k * 64 + j], sz);
            sh = fmaf(chw[f * 64 + k], lhw[k * 64 + j], sh);
        }
        g_Mz[idx] = sz;
        g_Mh[idx] = sh;
    }
    for (int j = t; j < 64; j += 128) {
        float sz = lzb[j], sh = lhb[j];
        for (int k = 0; k < 64; k++) {
            sz = fmaf(czb[k], lzw[k * 64 + j], sz);
            sh = fmaf(chb[k], lhw[k * 64 + j], sh);
        }
        g_cz[j] = sz;
        g_ch[j] = sh;
    }
    if (t == 0) {
        float m = attn[0];
        for (int p = 1; p < 12; p++) m = fmaxf(m, attn[p]);
        float e[12], s = 0.f;
        for (int p = 0; p < 12; p++) { e[p] = __expf(attn[p] - m); s += e[p]; }
        float inv = 1.f / s;
        for (int p = 0; p < 12; p++) g_probs[p] = e[p] * inv;
    }
}

// ---------------- CSR build ----------------
__global__ void k_clear() {
    int i = blockIdx.x * 256 + threadIdx.x;
    if (i < NN) g_cnt[i] = 0;
}

__global__ void k_hist(const void* __restrict__ ei) {
    int e = blockIdx.x * 256 + threadIdx.x;
    int is64 = g_is64;
    if (e < NE) {
        int d = load_edge(ei, (long long)NE + e, is64);
        atomicAdd(&g_cnt[d], 1);
    }
}

__global__ void k_scan1() {
    __shared__ int sh[256];
    int t = threadIdx.x;
    int i = blockIdx.x * 256 + t;
    int v = (i < NN) ? g_cnt[i] : 0;
    sh[t] = v;
    __syncthreads();
    for (int off = 1; off < 256; off <<= 1) {
        int add = (t >= off) ? sh[t - off] : 0;
        __syncthreads();
        sh[t] += add;
        __syncthreads();
    }
    int incl = sh[t];
    if (i < NN) g_rowptr[i] = incl - v;
    if (t == 255) g_bsum[blockIdx.x] = incl;
}

__global__ void k_scan2() {
    __shared__ int sh[512];
    int t = threadIdx.x;
    int v = (t < NB_SCAN) ? g_bsum[t] : 0;
    sh[t] = v;
    __syncthreads();
    for (int off = 1; off < 512; off <<= 1) {
        int add = (t >= off) ? sh[t - off] : 0;
        __syncthreads();
        sh[t] += add;
        __syncthreads();
    }
    g_boff[t] = sh[t] - v;
}

__global__ void k_scan3() {
    int i = blockIdx.x * 256 + threadIdx.x;
    if (i < NN) {
        int r = g_rowptr[i] + g_boff[i >> 8];
        g_rowptr[i] = r;
        g_cursor[i] = r;
        g_dinv[i] = rsqrtf((float)(g_cnt[i] + 1));  // +1 self-loop
    }
    if (i == 0) g_rowptr[NN] = NE;
}

// reset cursors from rowptr (makes a duplicated k_fill safe)
__global__ void k_rescur() {
    int i = blockIdx.x * 256 + threadIdx.x;
    if (i < NN) g_cursor[i] = g_rowptr[i];
}

__global__ void k_fill(const void* __restrict__ ei) {
    int e = blockIdx.x * 256 + threadIdx.x;
    int is64 = g_is64;
    if (e < NE) {
        int s = load_edge(ei, e, is64);
        int d = load_edge(ei, (long long)NE + e, is64);
        int pos = atomicAdd(&g_cursor[d], 1);
        g_csr_src[pos] = s;
        g_csr_wt[pos]  = g_dinv[s];
    }
}

// ---------------- K_spmm: Y[d] = dn * ( dn*x[d] + sum_s dinv[s]*xh[s] ) ----------------
__device__ __forceinline__ void acc_edge(float wt, const uint32_t* __restrict__ xs,
                                         int lane, float* acc) {
#pragma unroll
    for (int i = 0; i < 3; i++) {
        uint32_t v = __ldg(xs + lane + 32 * i);
        __half2 h = *reinterpret_cast<__half2*>(&v);
        float2 f = __half22float2(h);
        acc[2 * i + 0] = fmaf(wt, f.x, acc[2 * i + 0]);
        acc[2 * i + 1] = fmaf(wt, f.y, acc[2 * i + 1]);
    }
}

__global__ void __launch_bounds__(256) k_spmm(const float* __restrict__ x) {
    int w = blockIdx.x * 8 + (threadIdx.x >> 5);
    int lane = threadIdx.x & 31;
    if (w >= NN) return;

    float dn = g_dinv[w];
    int b = g_rowptr[w];
    int e = g_rowptr[w + 1];

    float acc[6];
    const float2* xr = reinterpret_cast<const float2*>(x + (size_t)w * 192);
#pragma unroll
    for (int i = 0; i < 3; i++) {
        float2 f = __ldg(xr + lane + 32 * i);
        acc[2 * i + 0] = dn * f.x;
        acc[2 * i + 1] = dn * f.y;
    }

    int t = b;
    for (; t + 3 < e; t += 4) {
        int   s0 = g_csr_src[t],     s1 = g_csr_src[t + 1];
        int   s2 = g_csr_src[t + 2], s3 = g_csr_src[t + 3];
        float w0 = g_csr_wt[t],      w1 = g_csr_wt[t + 1];
        float w2 = g_csr_wt[t + 2],  w3 = g_csr_wt[t + 3];
        acc_edge(w0, g_xh + (size_t)s0 * 96, lane, acc);
        acc_edge(w1, g_xh + (size_t)s1 * 96, lane, acc);
        acc_edge(w2, g_xh + (size_t)s2 * 96, lane, acc);
        acc_edge(w3, g_xh + (size_t)s3 * 96, lane, acc);
    }
    for (; t < e; ++t) {
        acc_edge(g_csr_wt[t], g_xh + (size_t)g_csr_src[t] * 96, lane, acc);
    }

    float* yr = g_Y + (size_t)w * 192;
#pragma unroll
    for (int i = 0; i < 3; i++) {
        int k = 2 * (lane + 32 * i);        // k = f*12 + p in source layout
        int f0 = k / 12,       p0 = k - f0 * 12;
        int f1 = (k + 1) / 12, p1 = (k + 1) - f1 * 12;
        __stcs(yr + p0 * 16 + f0, dn * acc[2 * i + 0]);
        __stcs(yr + p1 * 16 + f1, dn * acc[2 * i + 1]);
    }
}

// ---------------- K_dense: 16 threads/node, 4 cols/thread — fits 32-reg cap ----------------
__global__ void __launch_bounds__(128) k_dense(const float* __restrict__ outw,
                                               const float* __restrict__ outb,
                                               float* __restrict__ out) {
    __shared__ __align__(16) float sMz[16 * 64];   // [f][j]
    __shared__ __align__(16) float sMh[16 * 64];
    __shared__ __align__(16) float scz[64];
    __shared__ __align__(16) float sch[64];
    __shared__ __align__(16) float sOw[256];       // [j][phase]
    __shared__ float sOb[4], sp[12];

    int t = threadIdx.x;
    for (int idx = t; idx < 1024; idx += 128) { sMz[idx] = g_Mz[idx]; sMh[idx] = g_Mh[idx]; }
    for (int idx = t; idx < 64; idx += 128) { scz[idx] = g_cz[idx]; sch[idx] = g_ch[idx]; }
    for (int idx = t; idx < 256; idx += 128) sOw[idx] = outw[idx];
    if (t < 4) sOb[t] = outb[t];
    if (t < 12) sp[t] = g_probs[t];
    __syncthreads();

    int gid = blockIdx.x * 128 + t;
    int n  = gid >> 4;              // node (16 threads each)
    int jg = gid & 15;              // column group: cols 4*jg .. 4*jg+3
    if (n >= NN) return;

    const float4* yr  = reinterpret_cast<const float4*>(g_Y + (size_t)n * 192);
    const float4* mz4 = reinterpret_cast<const float4*>(sMz);  // [f][16]
    const float4* mh4 = reinterpret_cast<const float4*>(sMh);
    const float4* cz4 = reinterpret_cast<const float4*>(scz);
    const float4* ch4 = reinterpret_cast<const float4*>(sch);

    float hac0 = 0.f, hac1 = 0.f, hac2 = 0.f, hac3 = 0.f;

    for (int p = 0; p < 12; p++) {
        float4 c = cz4[jg];
        float za0 = c.x, za1 = c.y, za2 = c.z, za3 = c.w;
        c = ch4[jg];
        float ha0 = c.x, ha1 = c.y, ha2 = c.z, ha3 = c.w;

#pragma unroll
        for (int q = 0; q < 4; q++) {
            float4 y = yr[p * 4 + q];          // feats 4q..4q+3
#pragma unroll
            for (int r = 0; r < 4; r++) {
                float yv = (r == 0) ? y.x : (r == 1) ? y.y : (r == 2) ? y.z : y.w;
                int f = 4 * q + r;
                float4 wz = mz4[f * 16 + jg];
                float4 wh = mh4[f * 16 + jg];
                za0 = fmaf(yv, wz.x, za0); za1 = fmaf(yv, wz.y, za1);
                za2 = fmaf(yv, wz.z, za2); za3 = fmaf(yv, wz.w, za3);
                ha0 = fmaf(yv, wh.x, ha0); ha1 = fmaf(yv, wh.y, ha1);
                ha2 = fmaf(yv, wh.z, ha2); ha3 = fmaf(yv, wh.w, ha3);
            }
        }
        float prh = 0.5f * sp[p];
        // pr*(1-sigmoid(z)) = pr*0.5*(1-tanh(z/2))
        hac0 = fmaf(prh * (1.f - tanh_fast(0.5f * za0)), tanh_fast(ha0), hac0);
        hac1 = fmaf(prh * (1.f - tanh_fast(0.5f * za1)), tanh_fast(ha1), hac1);
        hac2 = fmaf(prh * (1.f - tanh_fast(0.5f * za2)), tanh_fast(ha2), hac2);
        hac3 = fmaf(prh * (1.f - tanh_fast(0.5f * za3)), tanh_fast(ha3), hac3);
    }

    // output head: relu -> 64x4 -> reduce over 16 threads -> softmax(4)
    float lg0 = 0.f, lg1 = 0.f, lg2 = 0.f, lg3 = 0.f;
    const float4* ow4 = reinterpret_cast<const float4*>(sOw);
#pragma unroll
    for (int r = 0; r < 4; r++) {
        float h = (r == 0) ? hac0 : (r == 1) ? hac1 : (r == 2) ? hac2 : hac3;
        h = fmaxf(h, 0.f);
        float4 w = ow4[jg * 4 + r];            // phases for col jg*4+r
        lg0 = fmaf(h, w.x, lg0);
        lg1 = fmaf(h, w.y, lg1);
        lg2 = fmaf(h, w.z, lg2);
        lg3 = fmaf(h, w.w, lg3);
    }
#pragma unroll
    for (int off = 8; off > 0; off >>= 1) {
        lg0 += __shfl_down_sync(0xffffffffu, lg0, off, 16);
        lg1 += __shfl_down_sync(0xffffffffu, lg1, off, 16);
        lg2 += __shfl_down_sync(0xffffffffu, lg2, off, 16);
        lg3 += __shfl_down_sync(0xffffffffu, lg3, off, 16);
    }
    if (jg == 0) {
        lg0 += sOb[0]; lg1 += sOb[1]; lg2 += sOb[2]; lg3 += sOb[3];
        float m = fmaxf(fmaxf(lg0, lg1), fmaxf(lg2, lg3));
        float e0 = __expf(lg0 - m), e1 = __expf(lg1 - m);
        float e2 = __expf(lg2 - m), e3 = __expf(lg3 - m);
        float inv = __fdividef(1.f, e0 + e1 + e2 + e3);
        reinterpret_cast<float4*>(out)[n] = make_float4(e0 * inv, e1 * inv, e2 * inv, e3 * inv);
    }
}

// ---------------- launch ----------------
extern "C" void kernel_launch(void* const* d_in, const int* in_sizes, int n_in,
                              void* d_out, int out_size) {
    const float* x    = (const float*)d_in[0];
    const void*  ei   = d_in[1];                    // int32 or int64, detected on device
    const float* attn = (const float*)d_in[2];
    const float* czw  = (const float*)d_in[3];
    const float* czb  = (const float*)d_in[4];
    // d_in[5], d_in[6] (conv_r_*) and d_in[11], d_in[12] (lin_r_*) are dead code: H0 == 0
    const float* chw  = (const float*)d_in[7];
    const float* chb  = (const float*)d_in[8];
    const float* lzw  = (const float*)d_in[9];
    const float* lzb  = (const float*)d_in[10];
    const float* lhw  = (const float*)d_in[13];
    const float* lhb  = (const float*)d_in[14];
    const float* ow   = (const float*)d_in[15];
    const float* ob   = (const float*)d_in[16];
    float* out = (float*)d_out;

    k_detect<<<1, 256>>>((const unsigned int*)ei);
    k_prep <<<1, 128>>>(attn, czw, czb, chw, chb, lzw, lzb, lhw, lhb);
    k_half <<<(NN * 96 + 255) / 256, 256>>>(x);
    k_clear<<<NB_SCAN, 256>>>();
    k_hist <<<(NE + 255) / 256, 256>>>(ei);
    k_scan1<<<NB_SCAN, 256>>>();
    k_scan2<<<1, 512>>>();
    k_scan3<<<NB_SCAN, 256>>>();
    // DIAGNOSTIC: duplicate k_fill to measure its wall-clock cost via total delta.
    // k_rescur resets cursors so the real k_fill below produces an identical CSR.
    k_fill <<<(NE + 255) / 256, 256>>>(ei);
    k_rescur<<<NB_SCAN, 256>>>();
    k_fill <<<(NE + 255) / 256, 256>>>(ei);
    k_spmm <<<(NN + 7) / 8, 256>>>(x);
    k_dense<<<(NN * 16 + 127) / 128, 128>>>(ow, ob, out);
}

// round 14
// speedup vs baseline: 17.1047x; 1.0755x over previous
#include <cuda_runtime.h>
#include <cuda_fp16.h>
#include <cstdint>

#define NN 100000
#define NE 1600000
#define NB_SCAN 391   // ceil(NN/256)

// ---------------- scratch (static device globals; no allocation) ----------------
__device__ int      g_is64;
__device__ int      g_cnt[NN];
__device__ int      g_cursor[NN];
__device__ int      g_rowptr[NN + 1];
__device__ float    g_dinv[NN];
__device__ int      g_csr_src[NE];
__device__ uint32_t g_xh[(size_t)NN * 96];        // X in fp16x2: 96 half2 per node
__device__ float    g_Y[(size_t)NN * 192];        // [n][p][f], p=12, f=16
__device__ int      g_bsum[512];
__device__ int      g_boff[512];
__device__ float    g_Mz[16 * 64];
__device__ float    g_Mh[16 * 64];
__device__ float    g_cz[64];
__device__ float    g_ch[64];
__device__ float    g_probs[12];

// edge_index may be int32 or int64 depending on JAX x64 config; detect at runtime.
__device__ __forceinline__ int load_edge(const void* ei, long long pos, int is64) {
    if (is64) return (int)((const long long*)ei)[pos];
    return ((const int*)ei)[pos];
}

__device__ __forceinline__ float tanh_fast(float v) {
    float r;
    asm("tanh.approx.f32 %0, %1;" : "=f"(r) : "f"(v));
    return r;
}

// ---------------- K_detect: int64 vs int32 edge dtype ----------------
__global__ void k_detect(const unsigned int* __restrict__ ew) {
    __shared__ unsigned int sh[256];
    int t = threadIdx.x;
    unsigned int v = 0;
    for (int i = t; i < 4096; i += 256) v |= ew[2 * i + 1];
    sh[t] = v;
    __syncthreads();
    for (int off = 128; off > 0; off >>= 1) {
        if (t < off) sh[t] |= sh[t + off];
        __syncthreads();
    }
    if (t == 0) g_is64 = (sh[0] == 0u) ? 1 : 0;
}

// ---------------- K_half: X fp32 -> fp16x2 (streaming) ----------------
__global__ void __launch_bounds__(256) k_half(const float* __restrict__ x) {
    size_t i = (size_t)blockIdx.x * 256 + threadIdx.x;
    if (i < (size_t)NN * 96) {
        float2 f = reinterpret_cast<const float2*>(x)[i];
        __half2 h = __float22half2_rn(f);
        g_xh[i] = *reinterpret_cast<uint32_t*>(&h);
    }
}

// ---------------- K0: fold weights + softmax(attn) ----------------
__global__ void k_prep(const float* __restrict__ attn,
                       const float* __restrict__ czw, const float* __restrict__ czb,
                       const float* __restrict__ chw, const float* __restrict__ chb,
                       const float* __restrict__ lzw, const float* __restrict__ lzb,
                       const float* __restrict__ lhw, const float* __restrict__ lhb) {
    int t = threadIdx.x;
    for (int idx = t; idx < 1024; idx += 128) {
        int f = idx >> 6, j = idx & 63;
        float sz = 0.f, sh = 0.f;
        for (int k = 0; k < 64; k++) {
            sz = fmaf(czw[f * 64 + k], lzw[k * 64 + j], sz);
            sh = fmaf(chw[f * 64 + k], lhw[k * 64 + j], sh);
        }
        g_Mz[idx] = sz;
        g_Mh[idx] = sh;
    }
    for (int j = t; j < 64; j += 128) {
        float sz = lzb[j], sh = lhb[j];
        for (int k = 0; k < 64; k++) {
            sz = fmaf(czb[k], lzw[k * 64 + j], sz);
            sh = fmaf(chb[k], lhw[k * 64 + j], sh);
        }
        g_cz[j] = sz;
        g_ch[j] = sh;
    }
    if (t == 0) {
        float m = attn[0];
        for (int p = 1; p < 12; p++) m = fmaxf(m, attn[p]);
        float e[12], s = 0.f;
        for (int p = 0; p < 12; p++) { e[p] = __expf(attn[p] - m); s += e[p]; }
        float inv = 1.f / s;
        for (int p = 0; p < 12; p++) g_probs[p] = e[p] * inv;
    }
}

// ---------------- CSR build ----------------
__global__ void k_clear() {
    int i = blockIdx.x * 256 + threadIdx.x;
    if (i < NN) g_cnt[i] = 0;
}

__global__ void k_hist(const void* __restrict__ ei) {
    int e = blockIdx.x * 256 + threadIdx.x;
    int is64 = g_is64;
    if (e < NE) {
        int d = load_edge(ei, (long long)NE + e, is64);
        atomicAdd(&g_cnt[d], 1);
    }
}

__global__ void k_scan1() {
    __shared__ int sh[256];
    int t = threadIdx.x;
    int i = blockIdx.x * 256 + t;
    int v = (i < NN) ? g_cnt[i] : 0;
    sh[t] = v;
    __syncthreads();
    for (int off = 1; off < 256; off <<= 1) {
        int add = (t >= off) ? sh[t - off] : 0;
        __syncthreads();
        sh[t] += add;
        __syncthreads();
    }
    int incl = sh[t];
    if (i < NN) g_rowptr[i] = incl - v;
    if (t == 255) g_bsum[blockIdx.x] = incl;
}

__global__ void k_scan2() {
    __shared__ int sh[512];
    int t = threadIdx.x;
    int v = (t < NB_SCAN) ? g_bsum[t] : 0;
    sh[t] = v;
    __syncthreads();
    for (int off = 1; off < 512; off <<= 1) {
        int add = (t >= off) ? sh[t - off] : 0;
        __syncthreads();
        sh[t] += add;
        __syncthreads();
    }
    g_boff[t] = sh[t] - v;
}

__global__ void k_scan3() {
    int i = blockIdx.x * 256 + threadIdx.x;
    if (i < NN) {
        int r = g_rowptr[i] + g_boff[i >> 8];
        g_rowptr[i] = r;
        g_cursor[i] = r;
        g_dinv[i] = rsqrtf((float)(g_cnt[i] + 1));  // +1 self-loop
    }
    if (i == 0) g_rowptr[NN] = NE;
}

__global__ void k_fill(const void* __restrict__ ei) {
    int e = blockIdx.x * 256 + threadIdx.x;
    int is64 = g_is64;
    if (e < NE) {
        int s = load_edge(ei, e, is64);
        int d = load_edge(ei, (long long)NE + e, is64);
        int pos = atomicAdd(&g_cursor[d], 1);
        g_csr_src[pos] = s;          // 4B scatter only; dinv[s] loaded in k_spmm
    }
}

// ---------------- K_spmm: Y[d] = dn * ( dn*x[d] + sum_s dinv[s]*xh[s] ) ----------------
__device__ __forceinline__ void acc_edge(float wt, const uint32_t* __restrict__ xs,
                                         int lane, float* acc) {
#pragma unroll
    for (int i = 0; i < 3; i++) {
        uint32_t v = __ldg(xs + lane + 32 * i);
        __half2 h = *reinterpret_cast<__half2*>(&v);
        float2 f = __half22float2(h);
        acc[2 * i + 0] = fmaf(wt, f.x, acc[2 * i + 0]);
        acc[2 * i + 1] = fmaf(wt, f.y, acc[2 * i + 1]);
    }
}

__global__ void __launch_bounds__(256) k_spmm(const float* __restrict__ x) {
    int w = blockIdx.x * 8 + (threadIdx.x >> 5);
    int lane = threadIdx.x & 31;
    if (w >= NN) return;

    float dn = g_dinv[w];
    int b = g_rowptr[w];
    int e = g_rowptr[w + 1];

    float acc[6];
    const float2* xr = reinterpret_cast<const float2*>(x + (size_t)w * 192);
#pragma unroll
    for (int i = 0; i < 3; i++) {
        float2 f = __ldg(xr + lane + 32 * i);
        acc[2 * i + 0] = dn * f.x;
        acc[2 * i + 1] = dn * f.y;
    }

    int t = b;
    for (; t + 3 < e; t += 4) {
        int s0 = g_csr_src[t],     s1 = g_csr_src[t + 1];
        int s2 = g_csr_src[t + 2], s3 = g_csr_src[t + 3];
        float w0 = __ldg(g_dinv + s0), w1 = __ldg(g_dinv + s1);   // warp-uniform broadcast
        float w2 = __ldg(g_dinv + s2), w3 = __ldg(g_dinv + s3);
        acc_edge(w0, g_xh + (size_t)s0 * 96, lane, acc);
        acc_edge(w1, g_xh + (size_t)s1 * 96, lane, acc);
        acc_edge(w2, g_xh + (size_t)s2 * 96, lane, acc);
        acc_edge(w3, g_xh + (size_t)s3 * 96, lane, acc);
    }
    for (; t < e; ++t) {
        int s0 = g_csr_src[t];
        acc_edge(__ldg(g_dinv + s0), g_xh + (size_t)s0 * 96, lane, acc);
    }

    float* yr = g_Y + (size_t)w * 192;
#pragma unroll
    for (int i = 0; i < 3; i++) {
        int k = 2 * (lane + 32 * i);        // k = f*12 + p in source layout
        int f0 = k / 12,       p0 = k - f0 * 12;
        int f1 = (k + 1) / 12, p1 = (k + 1) - f1 * 12;
        __stcs(yr + p0 * 16 + f0, dn * acc[2 * i + 0]);
        __stcs(yr + p1 * 16 + f1, dn * acc[2 * i + 1]);
    }
}

// ---------------- K_dense: 16 threads/node, 4 cols/thread — fits 32-reg cap ----------------
__global__ void __launch_bounds__(128) k_dense(const float* __restrict__ outw,
                                               const float* __restrict__ outb,
                                               float* __restrict__ out) {
    __shared__ __align__(16) float sMz[16 * 64];   // [f][j]
    __shared__ __align__(16) float sMh[16 * 64];
    __shared__ __align__(16) float scz[64];
    __shared__ __align__(16) float sch[64];
    __shared__ __align__(16) float sOw[256];       // [j][phase]
    __shared__ float sOb[4], sp[12];

    int t = threadIdx.x;
    for (int idx = t; idx < 1024; idx += 128) { sMz[idx] = g_Mz[idx]; sMh[idx] = g_Mh[idx]; }
    for (int idx = t; idx < 64; idx += 128) { scz[idx] = g_cz[idx]; sch[idx] = g_ch[idx]; }
    for (int idx = t; idx < 256; idx += 128) sOw[idx] = outw[idx];
    if (t < 4) sOb[t] = outb[t];
    if (t < 12) sp[t] = g_probs[t];
    __syncthreads();

    int gid = blockIdx.x * 128 + t;
    int n  = gid >> 4;              // node (16 threads each)
    int jg = gid & 15;              // column group: cols 4*jg .. 4*jg+3
    if (n >= NN) return;

    const float4* yr  = reinterpret_cast<const float4*>(g_Y + (size_t)n * 192);
    const float4* mz4 = reinterpret_cast<const float4*>(sMz);  // [f][16]
    const float4* mh4 = reinterpret_cast<const float4*>(sMh);
    const float4* cz4 = reinterpret_cast<const float4*>(scz);
    const float4* ch4 = reinterpret_cast<const float4*>(sch);

    float hac0 = 0.f, hac1 = 0.f, hac2 = 0.f, hac3 = 0.f;

    for (int p = 0; p < 12; p++) {
        float4 c = cz4[jg];
        float za0 = c.x, za1 = c.y, za2 = c.z, za3 = c.w;
        c = ch4[jg];
        float ha0 = c.x, ha1 = c.y, ha2 = c.z, ha3 = c.w;

#pragma unroll
        for (int q = 0; q < 4; q++) {
            float4 y = yr[p * 4 + q];          // feats 4q..4q+3
#pragma unroll
            for (int r = 0; r < 4; r++) {
                float yv = (r == 0) ? y.x : (r == 1) ? y.y : (r == 2) ? y.z : y.w;
                int f = 4 * q + r;
                float4 wz = mz4[f * 16 + jg];
                float4 wh = mh4[f * 16 + jg];
                za0 = fmaf(yv, wz.x, za0); za1 = fmaf(yv, wz.y, za1);
                za2 = fmaf(yv, wz.z, za2); za3 = fmaf(yv, wz.w, za3);
                ha0 = fmaf(yv, wh.x, ha0); ha1 = fmaf(yv, wh.y, ha1);
                ha2 = fmaf(yv, wh.z, ha2); ha3 = fmaf(yv, wh.w, ha3);
            }
        }
        float prh = 0.5f * sp[p];
        // pr*(1-sigmoid(z)) = pr*0.5*(1-tanh(z/2))
        hac0 = fmaf(prh * (1.f - tanh_fast(0.5f * za0)), tanh_fast(ha0), hac0);
        hac1 = fmaf(prh * (1.f - tanh_fast(0.5f * za1)), tanh_fast(ha1), hac1);
        hac2 = fmaf(prh * (1.f - tanh_fast(0.5f * za2)), tanh_fast(ha2), hac2);
        hac3 = fmaf(prh * (1.f - tanh_fast(0.5f * za3)), tanh_fast(ha3), hac3);
    }

    // output head: relu -> 64x4 -> reduce over 16 threads -> softmax(4)
    float lg0 = 0.f, lg1 = 0.f, lg2 = 0.f, lg3 = 0.f;
    const float4* ow4 = reinterpret_cast<const float4*>(sOw);
#pragma unroll
    for (int r = 0; r < 4; r++) {
        float h = (r == 0) ? hac0 : (r == 1) ? hac1 : (r == 2) ? hac2 : hac3;
        h = fmaxf(h, 0.f);
        float4 w = ow4[jg * 4 + r];            // phases for col jg*4+r
        lg0 = fmaf(h, w.x, lg0);
        lg1 = fmaf(h, w.y, lg1);
        lg2 = fmaf(h, w.z, lg2);
        lg3 = fmaf(h, w.w, lg3);
    }
#pragma unroll
    for (int off = 8; off > 0; off >>= 1) {
        lg0 += __shfl_down_sync(0xffffffffu, lg0, off, 16);
        lg1 += __shfl_down_sync(0xffffffffu, lg1, off, 16);
        lg2 += __shfl_down_sync(0xffffffffu, lg2, off, 16);
        lg3 += __shfl_down_sync(0xffffffffu, lg3, off, 16);
    }
    if (jg == 0) {
        lg0 += sOb[0]; lg1 += sOb[1]; lg2 += sOb[2]; lg3 += sOb[3];
        float m = fmaxf(fmaxf(lg0, lg1), fmaxf(lg2, lg3));
        float e0 = __expf(lg0 - m), e1 = __expf(lg1 - m);
        float e2 = __expf(lg2 - m), e3 = __expf(lg3 - m);
        float inv = __fdividef(1.f, e0 + e1 + e2 + e3);
        reinterpret_cast<float4*>(out)[n] = make_float4(e0 * inv, e1 * inv, e2 * inv, e3 * inv);
    }
}

// ---------------- launch ----------------
extern "C" void kernel_launch(void* const* d_in, const int* in_sizes, int n_in,
                              void* d_out, int out_size) {
    const float* x    = (const float*)d_in[0];
    const void*  ei   = d_in[1];                    // int32 or int64, detected on device
    const float* attn = (const float*)d_in[2];
    const float* czw  = (const float*)d_in[3];
    const float* czb  = (const float*)d_in[4];
    // d_in[5], d_in[6] (conv_r_*) and d_in[11], d_in[12] (lin_r_*) are dead code: H0 == 0
    const float* chw  = (const float*)d_in[7];
    const float* chb  = (const float*)d_in[8];
    const float* lzw  = (const float*)d_in[9];
    const float* lzb  = (const float*)d_in[10];
    const float* lhw  = (const float*)d_in[13];
    const float* lhb  = (const float*)d_in[14];
    const float* ow   = (const float*)d_in[15];
    const float* ob   = (const float*)d_in[16];
    float* out = (float*)d_out;

    k_detect<<<1, 256>>>((const unsigned int*)ei);
    k_prep <<<1, 128>>>(attn, czw, czb, chw, chb, lzw, lzb, lhw, lhb);
    k_half <<<(NN * 96 + 255) / 256, 256>>>(x);
    k_clear<<<NB_SCAN, 256>>>();
    k_hist <<<(NE + 255) / 256, 256>>>(ei);
    k_scan1<<<NB_SCAN, 256>>>();
    k_scan2<<<1, 512>>>();
    k_scan3<<<NB_SCAN, 256>>>();
    k_fill <<<(NE + 255) / 256, 256>>>(ei);
    k_spmm <<<(NN + 7) / 8, 256>>>(x);
    k_dense<<<(NN * 16 + 127) / 128, 128>>>(ow, ob, out);
}

// round 15
// speedup vs baseline: 19.2930x; 1.1279x over previous
#include <cuda_runtime.h>
#include <cuda_fp16.h>
#include <cstdint>

#define NN 100000
#define NE 1600000
#define NB_SCAN 391   // ceil(NN/256)

// ---------------- scratch (static device globals; no allocation) ----------------
__device__ int      g_is64;
__device__ int      g_cnt[NN];
__device__ int      g_cursor[NN];
__device__ int      g_rowptr[NN + 1];
__device__ float    g_dinv[NN];
__device__ int      g_csr_src[NE];
__device__ uint32_t g_xh[(size_t)NN * 96];        // X in fp16x2: 96 half2 per node
__device__ float    g_Y[(size_t)NN * 192];        // [n][p][f], p=12, f=16
__device__ int      g_bsum[512];
__device__ int      g_boff[512];
__device__ float    g_Mz[16 * 64];
__device__ float    g_Mh[16 * 64];
__device__ float    g_cz[64];
__device__ float    g_ch[64];
__device__ float    g_probs[12];

// edge_index may be int32 or int64 depending on JAX x64 config; detect at runtime.
__device__ __forceinline__ int load_edge(const void* ei, long long pos, int is64) {
    if (is64) return (int)((const long long*)ei)[pos];
    return ((const int*)ei)[pos];
}

__device__ __forceinline__ float tanh_fast(float v) {
    float r;
    asm("tanh.approx.f32 %0, %1;" : "=f"(r) : "f"(v));
    return r;
}

// ---------------- packed f32x2 helpers ----------------
__device__ __forceinline__ unsigned long long pack2(float v) {
    unsigned long long r;
    asm("mov.b64 %0, {%1, %1};" : "=l"(r) : "f"(v));
    return r;
}
__device__ __forceinline__ float2 unpack2(unsigned long long v) {
    float2 f;
    asm("mov.b64 {%0, %1}, %2;" : "=f"(f.x), "=f"(f.y) : "l"(v));
    return f;
}
#define FMA2(acc, a, b) asm("fma.rn.f32x2 %0, %1, %2, %0;" : "+l"(acc) : "l"(a), "l"(b))

// ---------------- K_detect: int64 vs int32 edge dtype ----------------
__global__ void k_detect(const unsigned int* __restrict__ ew) {
    __shared__ unsigned int sh[256];
    int t = threadIdx.x;
    unsigned int v = 0;
    for (int i = t; i < 4096; i += 256) v |= ew[2 * i + 1];
    sh[t] = v;
    __syncthreads();
    for (int off = 128; off > 0; off >>= 1) {
        if (t < off) sh[t] |= sh[t + off];
        __syncthreads();
    }
    if (t == 0) g_is64 = (sh[0] == 0u) ? 1 : 0;
}

// ---------------- K_half: X fp32 -> fp16x2 (streaming) ----------------
__global__ void __launch_bounds__(256) k_half(const float* __restrict__ x) {
    size_t i = (size_t)blockIdx.x * 256 + threadIdx.x;
    if (i < (size_t)NN * 96) {
        float2 f = reinterpret_cast<const float2*>(x)[i];
        __half2 h = __float22half2_rn(f);
        g_xh[i] = *reinterpret_cast<uint32_t*>(&h);
    }
}

// ---------------- K0: fold weights + softmax(attn) ----------------
__global__ void k_prep(const float* __restrict__ attn,
                       const float* __restrict__ czw, const float* __restrict__ czb,
                       const float* __restrict__ chw, const float* __restrict__ chb,
                       const float* __restrict__ lzw, const float* __restrict__ lzb,
                       const float* __restrict__ lhw, const float* __restrict__ lhb) {
    int t = threadIdx.x;
    for (int idx = t; idx < 1024; idx += 128) {
        int f = idx >> 6, j = idx & 63;
        float sz = 0.f, sh = 0.f;
        for (int k = 0; k < 64; k++) {
            sz = fmaf(czw[f * 64 + k], lzw[k * 64 + j], sz);
            sh = fmaf(chw[f * 64 + k], lhw[k * 64 + j], sh);
        }
        g_Mz[idx] = sz;
        g_Mh[idx] = sh;
    }
    for (int j = t; j < 64; j += 128) {
        float sz = lzb[j], sh = lhb[j];
        for (int k = 0; k < 64; k++) {
            sz = fmaf(czb[k], lzw[k * 64 + j], sz);
            sh = fmaf(chb[k], lhw[k * 64 + j], sh);
        }
        g_cz[j] = sz;
        g_ch[j] = sh;
    }
    if (t == 0) {
        float m = attn[0];
        for (int p = 1; p < 12; p++) m = fmaxf(m, attn[p]);
        float e[12], s = 0.f;
        for (int p = 0; p < 12; p++) { e[p] = __expf(attn[p] - m); s += e[p]; }
        float inv = 1.f / s;
        for (int p = 0; p < 12; p++) g_probs[p] = e[p] * inv;
    }
}

// ---------------- CSR build ----------------
__global__ void k_clear() {
    int i = blockIdx.x * 256 + threadIdx.x;
    if (i < NN) g_cnt[i] = 0;
}

__global__ void k_hist(const void* __restrict__ ei) {
    int e = blockIdx.x * 256 + threadIdx.x;
    int is64 = g_is64;
    if (e < NE) {
        int d = load_edge(ei, (long long)NE + e, is64);
        atomicAdd(&g_cnt[d], 1);
    }
}

__global__ void k_scan1() {
    __shared__ int sh[256];
    int t = threadIdx.x;
    int i = blockIdx.x * 256 + t;
    int v = (i < NN) ? g_cnt[i] : 0;
    sh[t] = v;
    __syncthreads();
    for (int off = 1; off < 256; off <<= 1) {
        int add = (t >= off) ? sh[t - off] : 0;
        __syncthreads();
        sh[t] += add;
        __syncthreads();
    }
    int incl = sh[t];
    if (i < NN) g_rowptr[i] = incl - v;
    if (t == 255) g_bsum[blockIdx.x] = incl;
}

__global__ void k_scan2() {
    __shared__ int sh[512];
    int t = threadIdx.x;
    int v = (t < NB_SCAN) ? g_bsum[t] : 0;
    sh[t] = v;
    __syncthreads();
    for (int off = 1; off < 512; off <<= 1) {
        int add = (t >= off) ? sh[t - off] : 0;
        __syncthreads();
        sh[t] += add;
        __syncthreads();
    }
    g_boff[t] = sh[t] - v;
}

__global__ void k_scan3() {
    int i = blockIdx.x * 256 + threadIdx.x;
    if (i < NN) {
        int r = g_rowptr[i] + g_boff[i >> 8];
        g_rowptr[i] = r;
        g_cursor[i] = r;
        g_dinv[i] = rsqrtf((float)(g_cnt[i] + 1));  // +1 self-loop
    }
    if (i == 0) g_rowptr[NN] = NE;
}

__global__ void k_fill(const void* __restrict__ ei) {
    int e = blockIdx.x * 256 + threadIdx.x;
    int is64 = g_is64;
    if (e < NE) {
        int s = load_edge(ei, e, is64);
        int d = load_edge(ei, (long long)NE + e, is64);
        int pos = atomicAdd(&g_cursor[d], 1);
        g_csr_src[pos] = s;          // 4B scatter only; dinv[s] loaded in k_spmm
    }
}

// ---------------- K_spmm: Y[d] = dn * ( dn*x[d] + sum_s dinv[s]*xh[s] ) ----------------
__device__ __forceinline__ void acc_edge(float wt, const uint32_t* __restrict__ xs,
                                         int lane, float* acc) {
#pragma unroll
    for (int i = 0; i < 3; i++) {
        uint32_t v = __ldg(xs + lane + 32 * i);
        __half2 h = *reinterpret_cast<__half2*>(&v);
        float2 f = __half22float2(h);
        acc[2 * i + 0] = fmaf(wt, f.x, acc[2 * i + 0]);
        acc[2 * i + 1] = fmaf(wt, f.y, acc[2 * i + 1]);
    }
}

__global__ void __launch_bounds__(256) k_spmm(const float* __restrict__ x) {
    int w = blockIdx.x * 8 + (threadIdx.x >> 5);
    int lane = threadIdx.x & 31;
    if (w >= NN) return;

    float dn = g_dinv[w];
    int b = g_rowptr[w];
    int e = g_rowptr[w + 1];

    float acc[6];
    const float2* xr = reinterpret_cast<const float2*>(x + (size_t)w * 192);
#pragma unroll
    for (int i = 0; i < 3; i++) {
        float2 f = __ldg(xr + lane + 32 * i);
        acc[2 * i + 0] = dn * f.x;
        acc[2 * i + 1] = dn * f.y;
    }

    int t = b;
    for (; t + 3 < e; t += 4) {
        int s0 = g_csr_src[t],     s1 = g_csr_src[t + 1];
        int s2 = g_csr_src[t + 2], s3 = g_csr_src[t + 3];
        float w0 = __ldg(g_dinv + s0), w1 = __ldg(g_dinv + s1);   // warp-uniform broadcast
        float w2 = __ldg(g_dinv + s2), w3 = __ldg(g_dinv + s3);
        acc_edge(w0, g_xh + (size_t)s0 * 96, lane, acc);
        acc_edge(w1, g_xh + (size_t)s1 * 96, lane, acc);
        acc_edge(w2, g_xh + (size_t)s2 * 96, lane, acc);
        acc_edge(w3, g_xh + (size_t)s3 * 96, lane, acc);
    }
    for (; t < e; ++t) {
        int s0 = g_csr_src[t];
        acc_edge(__ldg(g_dinv + s0), g_xh + (size_t)s0 * 96, lane, acc);
    }

    float* yr = g_Y + (size_t)w * 192;
#pragma unroll
    for (int i = 0; i < 3; i++) {
        int k = 2 * (lane + 32 * i);        // k = f*12 + p in source layout
        int f0 = k / 12,       p0 = k - f0 * 12;
        int f1 = (k + 1) / 12, p1 = (k + 1) - f1 * 12;
        __stcs(yr + p0 * 16 + f0, dn * acc[2 * i + 0]);
        __stcs(yr + p1 * 16 + f1, dn * acc[2 * i + 1]);
    }
}

// ---------------- K_dense: 16 threads/node, 4 cols/thread, packed f32x2 math ----------------
__global__ void __launch_bounds__(128) k_dense(const float* __restrict__ outw,
                                               const float* __restrict__ outb,
                                               float* __restrict__ out) {
    __shared__ __align__(16) float sMz[16 * 64];   // [f][j]
    __shared__ __align__(16) float sMh[16 * 64];
    __shared__ __align__(16) float scz[64];
    __shared__ __align__(16) float sch[64];
    __shared__ __align__(16) float sOw[256];       // [j][phase]
    __shared__ float sOb[4], sp[12];

    int t = threadIdx.x;
    for (int idx = t; idx < 1024; idx += 128) { sMz[idx] = g_Mz[idx]; sMh[idx] = g_Mh[idx]; }
    for (int idx = t; idx < 64; idx += 128) { scz[idx] = g_cz[idx]; sch[idx] = g_ch[idx]; }
    for (int idx = t; idx < 256; idx += 128) sOw[idx] = outw[idx];
    if (t < 4) sOb[t] = outb[t];
    if (t < 12) sp[t] = g_probs[t];
    __syncthreads();

    int gid = blockIdx.x * 128 + t;
    int n  = gid >> 4;              // node (16 threads each)
    int jg = gid & 15;              // column group: cols 4*jg .. 4*jg+3
    if (n >= NN) return;

    const float4*      yr  = reinterpret_cast<const float4*>(g_Y + (size_t)n * 192);
    const ulonglong2*  mz2 = reinterpret_cast<const ulonglong2*>(sMz);  // [f][16jg], 16B each
    const ulonglong2*  mh2 = reinterpret_cast<const ulonglong2*>(sMh);
    const unsigned long long* cz2 = reinterpret_cast<const unsigned long long*>(scz); // 32 col-pairs
    const unsigned long long* ch2 = reinterpret_cast<const unsigned long long*>(sch);

    float hac0 = 0.f, hac1 = 0.f, hac2 = 0.f, hac3 = 0.f;

    for (int p = 0; p < 12; p++) {
        unsigned long long za01 = cz2[2 * jg], za23 = cz2[2 * jg + 1];
        unsigned long long ha01 = ch2[2 * jg], ha23 = ch2[2 * jg + 1];

#pragma unroll
        for (int q = 0; q < 4; q++) {
            float4 y = yr[p * 4 + q];          // feats 4q..4q+3
#pragma unroll
            for (int r = 0; r < 4; r++) {
                float yv = (r == 0) ? y.x : (r == 1) ? y.y : (r == 2) ? y.z : y.w;
                int f = 4 * q + r;
                unsigned long long yy = pack2(yv);
                ulonglong2 wz = mz2[f * 16 + jg];
                ulonglong2 wh = mh2[f * 16 + jg];
                FMA2(za01, yy, wz.x);
                FMA2(za23, yy, wz.y);
                FMA2(ha01, yy, wh.x);
                FMA2(ha23, yy, wh.y);
            }
        }
        float prh = 0.5f * sp[p];
        // pr*(1-sigmoid(z)) = pr*0.5*(1-tanh(z/2))
        {
            float2 z = unpack2(za01), h = unpack2(ha01);
            hac0 = fmaf(prh * (1.f - tanh_fast(0.5f * z.x)), tanh_fast(h.x), hac0);
            hac1 = fmaf(prh * (1.f - tanh_fast(0.5f * z.y)), tanh_fast(h.y), hac1);
        }
        {
            float2 z = unpack2(za23), h = unpack2(ha23);
            hac2 = fmaf(prh * (1.f - tanh_fast(0.5f * z.x)), tanh_fast(h.x), hac2);
            hac3 = fmaf(prh * (1.f - tanh_fast(0.5f * z.y)), tanh_fast(h.y), hac3);
        }
    }

    // output head: relu -> 64x4 -> reduce over 16 threads -> softmax(4)
    float lg0 = 0.f, lg1 = 0.f, lg2 = 0.f, lg3 = 0.f;
    const float4* ow4 = reinterpret_cast<const float4*>(sOw);
#pragma unroll
    for (int r = 0; r < 4; r++) {
        float h = (r == 0) ? hac0 : (r == 1) ? hac1 : (r == 2) ? hac2 : hac3;
        h = fmaxf(h, 0.f);
        float4 w = ow4[jg * 4 + r];            // phases for col jg*4+r
        lg0 = fmaf(h, w.x, lg0);
        lg1 = fmaf(h, w.y, lg1);
        lg2 = fmaf(h, w.z, lg2);
        lg3 = fmaf(h, w.w, lg3);
    }
#pragma unroll
    for (int off = 8; off > 0; off >>= 1) {
        lg0 += __shfl_down_sync(0xffffffffu, lg0, off, 16);
        lg1 += __shfl_down_sync(0xffffffffu, lg1, off, 16);
        lg2 += __shfl_down_sync(0xffffffffu, lg2, off, 16);
        lg3 += __shfl_down_sync(0xffffffffu, lg3, off, 16);
    }
    if (jg == 0) {
        lg0 += sOb[0]; lg1 += sOb[1]; lg2 += sOb[2]; lg3 += sOb[3];
        float m = fmaxf(fmaxf(lg0, lg1), fmaxf(lg2, lg3));
        float e0 = __expf(lg0 - m), e1 = __expf(lg1 - m);
        float e2 = __expf(lg2 - m), e3 = __expf(lg3 - m);
        float inv = __fdividef(1.f, e0 + e1 + e2 + e3);
        reinterpret_cast<float4*>(out)[n] = make_float4(e0 * inv, e1 * inv, e2 * inv, e3 * inv);
    }
}

// ---------------- launch ----------------
extern "C" void kernel_launch(void* const* d_in, const int* in_sizes, int n_in,
                              void* d_out, int out_size) {
    const float* x    = (const float*)d_in[0];
    const void*  ei   = d_in[1];                    // int32 or int64, detected on device
    const float* attn = (const float*)d_in[2];
    const float* czw  = (const float*)d_in[3];
    const float* czb  = (const float*)d_in[4];
    // d_in[5], d_in[6] (conv_r_*) and d_in[11], d_in[12] (lin_r_*) are dead code: H0 == 0
    const float* chw  = (const float*)d_in[7];
    const float* chb  = (const float*)d_in[8];
    const float* lzw  = (const float*)d_in[9];
    const float* lzb  = (const float*)d_in[10];
    const float* lhw  = (const float*)d_in[13];
    const float* lhb  = (const float*)d_in[14];
    const float* ow   = (const float*)d_in[15];
    const float* ob   = (const float*)d_in[16];
    float* out = (float*)d_out;

    k_detect<<<1, 256>>>((const unsigned int*)ei);
    k_prep <<<1, 128>>>(attn, czw, czb, chw, chb, lzw, lzb, lhw, lhb);
    k_half <<<(NN * 96 + 255) / 256, 256>>>(x);
    k_clear<<<NB_SCAN, 256>>>();
    k_hist <<<(NE + 255) / 256, 256>>>(ei);
    k_scan1<<<NB_SCAN, 256>>>();
    k_scan2<<<1, 512>>>();
    k_scan3<<<NB_SCAN, 256>>>();
    k_fill <<<(NE + 255) / 256, 256>>>(ei);
    k_spmm <<<(NN + 7) / 8, 256>>>(x);
    k_dense<<<(NN * 16 + 127) / 128, 128>>>(ow, ob, out);
}

// round 17
// speedup vs baseline: 23.7859x; 1.2329x over previous
#include <cuda_runtime.h>
#include <cuda_fp16.h>
#include <cstdint>

#define NN 100000
#define NE 1600000
#define NB_SCAN 391   // ceil(NN/256)

// ---------------- scratch (static device globals; no allocation) ----------------
__device__ int      g_is64;
__device__ int      g_cnt[NN];
__device__ int      g_cursor[NN];
__device__ int      g_rowptr[NN + 1];
__device__ float    g_dinv[NN];
__device__ int      g_csr_src[NE];
__device__ uint32_t g_xh[(size_t)NN * 96];        // X in fp16x2: 96 half2 per node
__device__ float    g_Y[(size_t)NN * 192];        // [n][p][f], p=12, f=16
__device__ int      g_bsum[512];
__device__ int      g_boff[512];
__device__ float    g_Mz[16 * 64];
__device__ float    g_Mh[16 * 64];
__device__ float    g_cz[64];
__device__ float    g_ch[64];
__device__ float    g_probs[12];

// edge_index may be int32 or int64 depending on JAX x64 config; detect at runtime.
__device__ __forceinline__ int load_edge(const void* ei, long long pos, int is64) {
    if (is64) return (int)((const long long*)ei)[pos];
    return ((const int*)ei)[pos];
}

__device__ __forceinline__ float tanh_fast(float v) {
    float r;
    asm("tanh.approx.f32 %0, %1;" : "=f"(r) : "f"(v));
    return r;
}

// ---------------- packed f32x2 helpers ----------------
__device__ __forceinline__ unsigned long long pack2(float v) {
    unsigned long long r;
    asm("mov.b64 %0, {%1, %1};" : "=l"(r) : "f"(v));
    return r;
}
__device__ __forceinline__ float2 unpack2(unsigned long long v) {
    float2 f;
    asm("mov.b64 {%0, %1}, %2;" : "=f"(f.x), "=f"(f.y) : "l"(v));
    return f;
}
#define FMA2(acc, a, b) asm("fma.rn.f32x2 %0, %1, %2, %0;" : "+l"(acc) : "l"(a), "l"(b))

// ---------------- K_detect: int64 vs int32 edge dtype ----------------
__global__ void k_detect(const unsigned int* __restrict__ ew) {
    __shared__ unsigned int sh[256];
    int t = threadIdx.x;
    unsigned int v = 0;
    for (int i = t; i < 4096; i += 256) v |= ew[2 * i + 1];
    sh[t] = v;
    __syncthreads();
    for (int off = 128; off > 0; off >>= 1) {
        if (t < off) sh[t] |= sh[t + off];
        __syncthreads();
    }
    if (t == 0) g_is64 = (sh[0] == 0u) ? 1 : 0;
}

// ---------------- K_half: X fp32 -> fp16x2 (streaming) ----------------
__global__ void __launch_bounds__(256) k_half(const float* __restrict__ x) {
    size_t i = (size_t)blockIdx.x * 256 + threadIdx.x;
    if (i < (size_t)NN * 96) {
        float2 f = reinterpret_cast<const float2*>(x)[i];
        __half2 h = __float22half2_rn(f);
        g_xh[i] = *reinterpret_cast<uint32_t*>(&h);
    }
}

// ---------------- K0: fold weights + softmax(attn) ----------------
__global__ void k_prep(const float* __restrict__ attn,
                       const float* __restrict__ czw, const float* __restrict__ czb,
                       const float* __restrict__ chw, const float* __restrict__ chb,
                       const float* __restrict__ lzw, const float* __restrict__ lzb,
                       const float* __restrict__ lhw, const float* __restrict__ lhb) {
    int t = threadIdx.x;
    for (int idx = t; idx < 1024; idx += 128) {
        int f = idx >> 6, j = idx & 63;
        float sz = 0.f, sh = 0.f;
        for (int k = 0; k < 64; k++) {
            sz = fmaf(czw[f * 64 + k], lzw[k * 64 + j], sz);
            sh = fmaf(chw[f * 64 + k], lhw[k * 64 + j], sh);
        }
        g_Mz[idx] = sz;
        g_Mh[idx] = sh;
    }
    for (int j = t; j < 64; j += 128) {
        float sz = lzb[j], sh = lhb[j];
        for (int k = 0; k < 64; k++) {
            sz = fmaf(czb[k], lzw[k * 64 + j], sz);
            sh = fmaf(chb[k], lhw[k * 64 + j], sh);
        }
        g_cz[j] = sz;
        g_ch[j] = sh;
    }
    if (t == 0) {
        float m = attn[0];
        for (int p = 1; p < 12; p++) m = fmaxf(m, attn[p]);
        float e[12], s = 0.f;
        for (int p = 0; p < 12; p++) { e[p] = __expf(attn[p] - m); s += e[p]; }
        float inv = 1.f / s;
        for (int p = 0; p < 12; p++) g_probs[p] = e[p] * inv;
    }
}

// ---------------- CSR build ----------------
__global__ void k_clear() {
    int i = blockIdx.x * 256 + threadIdx.x;
    if (i < NN) g_cnt[i] = 0;
}

__global__ void k_hist(const void* __restrict__ ei) {
    int e = blockIdx.x * 256 + threadIdx.x;
    int is64 = g_is64;
    if (e < NE) {
        int d = load_edge(ei, (long long)NE + e, is64);
        atomicAdd(&g_cnt[d], 1);
    }
}

__global__ void k_scan1() {
    __shared__ int sh[256];
    int t = threadIdx.x;
    int i = blockIdx.x * 256 + t;
    int v = (i < NN) ? g_cnt[i] : 0;
    sh[t] = v;
    __syncthreads();
    for (int off = 1; off < 256; off <<= 1) {
        int add = (t >= off) ? sh[t - off] : 0;
        __syncthreads();
        sh[t] += add;
        __syncthreads();
    }
    int incl = sh[t];
    if (i < NN) g_rowptr[i] = incl - v;
    if (t == 255) g_bsum[blockIdx.x] = incl;
}

__global__ void k_scan2() {
    __shared__ int sh[512];
    int t = threadIdx.x;
    int v = (t < NB_SCAN) ? g_bsum[t] : 0;
    sh[t] = v;
    __syncthreads();
    for (int off = 1; off < 512; off <<= 1) {
        int add = (t >= off) ? sh[t - off] : 0;
        __syncthreads();
        sh[t] += add;
        __syncthreads();
    }
    g_boff[t] = sh[t] - v;
}

__global__ void k_scan3() {
    int i = blockIdx.x * 256 + threadIdx.x;
    if (i < NN) {
        int r = g_rowptr[i] + g_boff[i >> 8];
        g_rowptr[i] = r;
        g_cursor[i] = r;
        g_dinv[i] = rsqrtf((float)(g_cnt[i] + 1));  // +1 self-loop
    }
    if (i == 0) g_rowptr[NN] = NE;
}

__global__ void k_fill(const void* __restrict__ ei) {
    int e = blockIdx.x * 256 + threadIdx.x;
    int is64 = g_is64;
    if (e < NE) {
        int s = load_edge(ei, e, is64);
        int d = load_edge(ei, (long long)NE + e, is64);
        int pos = atomicAdd(&g_cursor[d], 1);
        g_csr_src[pos] = s;          // 4B scatter only; dinv[s] loaded in k_spmm
    }
}

// ---------------- K_spmm: Y[d] = dn * ( dn*x[d] + sum_s dinv[s]*xh[s] ) ----------------
__device__ __forceinline__ void acc_edge(float wt, const uint32_t* __restrict__ xs,
                                         int lane, float* acc) {
#pragma unroll
    for (int i = 0; i < 3; i++) {
        uint32_t v = __ldg(xs + lane + 32 * i);
        __half2 h = *reinterpret_cast<__half2*>(&v);
        float2 f = __half22float2(h);
        acc[2 * i + 0] = fmaf(wt, f.x, acc[2 * i + 0]);
        acc[2 * i + 1] = fmaf(wt, f.y, acc[2 * i + 1]);
    }
}

__global__ void __launch_bounds__(256) k_spmm(const float* __restrict__ x) {
    int w = blockIdx.x * 8 + (threadIdx.x >> 5);
    int lane = threadIdx.x & 31;
    if (w >= NN) return;

    float dn = g_dinv[w];
    int b = g_rowptr[w];
    int e = g_rowptr[w + 1];

    float acc[6];
    const float2* xr = reinterpret_cast<const float2*>(x + (size_t)w * 192);
#pragma unroll
    for (int i = 0; i < 3; i++) {
        float2 f = __ldg(xr + lane + 32 * i);
        acc[2 * i + 0] = dn * f.x;
        acc[2 * i + 1] = dn * f.y;
    }

    int t = b;
    for (; t + 3 < e; t += 4) {
        int s0 = g_csr_src[t],     s1 = g_csr_src[t + 1];
        int s2 = g_csr_src[t + 2], s3 = g_csr_src[t + 3];
        float w0 = __ldg(g_dinv + s0), w1 = __ldg(g_dinv + s1);   // warp-uniform broadcast
        float w2 = __ldg(g_dinv + s2), w3 = __ldg(g_dinv + s3);
        acc_edge(w0, g_xh + (size_t)s0 * 96, lane, acc);
        acc_edge(w1, g_xh + (size_t)s1 * 96, lane, acc);
        acc_edge(w2, g_xh + (size_t)s2 * 96, lane, acc);
        acc_edge(w3, g_xh + (size_t)s3 * 96, lane, acc);
    }
    for (; t < e; ++t) {
        int s0 = g_csr_src[t];
        acc_edge(__ldg(g_dinv + s0), g_xh + (size_t)s0 * 96, lane, acc);
    }

    float* yr = g_Y + (size_t)w * 192;
#pragma unroll
    for (int i = 0; i < 3; i++) {
        int k = 2 * (lane + 32 * i);        // k = f*12 + p in source layout
        int f0 = k / 12,       p0 = k - f0 * 12;
        int f1 = (k + 1) / 12, p1 = (k + 1) - f1 * 12;
        __stcs(yr + p0 * 16 + f0, dn * acc[2 * i + 0]);
        __stcs(yr + p1 * 16 + f1, dn * acc[2 * i + 1]);
    }
}

// ---------------- K_dense: 16 threads/node, smem-staged Y, packed f32x2 math ----------------
__global__ void __launch_bounds__(128) k_dense(const float* __restrict__ outw,
                                               const float* __restrict__ outb,
                                               float* __restrict__ out) {
    __shared__ __align__(16) float sMz[16 * 64];   // [f][j]
    __shared__ __align__(16) float sMh[16 * 64];
    __shared__ __align__(16) float scz[64];
    __shared__ __align__(16) float sch[64];
    __shared__ __align__(16) float sOw[256];       // [j][phase]
    __shared__ __align__(16) float sY[8 * 192];    // 8 nodes' Y rows (6 KB)
    __shared__ float sOb[4], sp[12];

    int t = threadIdx.x;
    for (int idx = t; idx < 1024; idx += 128) { sMz[idx] = g_Mz[idx]; sMh[idx] = g_Mh[idx]; }
    for (int idx = t; idx < 64; idx += 128) { scz[idx] = g_cz[idx]; sch[idx] = g_ch[idx]; }
    for (int idx = t; idx < 256; idx += 128) sOw[idx] = outw[idx];
    if (t < 4) sOb[t] = outb[t];
    if (t < 12) sp[t] = g_probs[t];

    // stage 8 nodes' Y rows (coalesced float4 copy); NN % 8 == 0
    {
        const float4* gy4 = reinterpret_cast<const float4*>(g_Y + (size_t)blockIdx.x * 8 * 192);
        float4* sy4w = reinterpret_cast<float4*>(sY);
#pragma unroll
        for (int i = 0; i < 3; i++)
            sy4w[t + 128 * i] = gy4[t + 128 * i];   // 384 float4 = 8*48
    }
    __syncthreads();

    int n  = t >> 4;                // node within block (0..7)
    int jg = t & 15;                // column group: cols 4*jg .. 4*jg+3

    const float4*      yr  = reinterpret_cast<const float4*>(sY + n * 192);
    const ulonglong2*  mz2 = reinterpret_cast<const ulonglong2*>(sMz);  // [f][16jg], 16B each
    const ulonglong2*  mh2 = reinterpret_cast<const ulonglong2*>(sMh);
    const unsigned long long* cz2 = reinterpret_cast<const unsigned long long*>(scz); // 32 col-pairs
    const unsigned long long* ch2 = reinterpret_cast<const unsigned long long*>(sch);

    float hac0 = 0.f, hac1 = 0.f, hac2 = 0.f, hac3 = 0.f;

    for (int p = 0; p < 12; p++) {
        unsigned long long za01 = cz2[2 * jg], za23 = cz2[2 * jg + 1];
        unsigned long long ha01 = ch2[2 * jg], ha23 = ch2[2 * jg + 1];

#pragma unroll
        for (int q = 0; q < 4; q++) {
            float4 y = yr[p * 4 + q];          // feats 4q..4q+3 (smem broadcast)
#pragma unroll
            for (int r = 0; r < 4; r++) {
                float yv = (r == 0) ? y.x : (r == 1) ? y.y : (r == 2) ? y.z : y.w;
                int f = 4 * q + r;
                unsigned long long yy = pack2(yv);
                ulonglong2 wz = mz2[f * 16 + jg];
                ulonglong2 wh = mh2[f * 16 + jg];
                FMA2(za01, yy, wz.x);
                FMA2(za23, yy, wz.y);
                FMA2(ha01, yy, wh.x);
                FMA2(ha23, yy, wh.y);
            }
        }
        float prh = 0.5f * sp[p];
        // pr*(1-sigmoid(z)) = pr*0.5*(1-tanh(z/2))
        {
            float2 z = unpack2(za01), h = unpack2(ha01);
            hac0 = fmaf(prh * (1.f - tanh_fast(0.5f * z.x)), tanh_fast(h.x), hac0);
            hac1 = fmaf(prh * (1.f - tanh_fast(0.5f * z.y)), tanh_fast(h.y), hac1);
        }
        {
            float2 z = unpack2(za23), h = unpack2(ha23);
            hac2 = fmaf(prh * (1.f - tanh_fast(0.5f * z.x)), tanh_fast(h.x), hac2);
            hac3 = fmaf(prh * (1.f - tanh_fast(0.5f * z.y)), tanh_fast(h.y), hac3);
        }
    }

    // output head: relu -> 64x4 -> reduce over 16 threads -> softmax(4)
    float lg0 = 0.f, lg1 = 0.f, lg2 = 0.f, lg3 = 0.f;
    const float4* ow4 = reinterpret_cast<const float4*>(sOw);
#pragma unroll
    for (int r = 0; r < 4; r++) {
        float h = (r == 0) ? hac0 : (r == 1) ? hac1 : (r == 2) ? hac2 : hac3;
        h = fmaxf(h, 0.f);
        float4 w = ow4[jg * 4 + r];            // phases for col jg*4+r
        lg0 = fmaf(h, w.x, lg0);
        lg1 = fmaf(h, w.y, lg1);
        lg2 = fmaf(h, w.z, lg2);
        lg3 = fmaf(h, w.w, lg3);
    }
#pragma unroll
    for (int off = 8; off > 0; off >>= 1) {
        lg0 += __shfl_down_sync(0xffffffffu, lg0, off, 16);
        lg1 += __shfl_down_sync(0xffffffffu, lg1, off, 16);
        lg2 += __shfl_down_sync(0xffffffffu, lg2, off, 16);
        lg3 += __shfl_down_sync(0xffffffffu, lg3, off, 16);
    }
    if (jg == 0) {
        int node = blockIdx.x * 8 + n;
        lg0 += sOb[0]; lg1 += sOb[1]; lg2 += sOb[2]; lg3 += sOb[3];
        float m = fmaxf(fmaxf(lg0, lg1), fmaxf(lg2, lg3));
        float e0 = __expf(lg0 - m), e1 = __expf(lg1 - m);
        float e2 = __expf(lg2 - m), e3 = __expf(lg3 - m);
        float inv = __fdividef(1.f, e0 + e1 + e2 + e3);
        reinterpret_cast<float4*>(out)[node] = make_float4(e0 * inv, e1 * inv, e2 * inv, e3 * inv);
    }
}

// ---------------- launch ----------------
extern "C" void kernel_launch(void* const* d_in, const int* in_sizes, int n_in,
                              void* d_out, int out_size) {
    const float* x    = (const float*)d_in[0];
    const void*  ei   = d_in[1];                    // int32 or int64, detected on device
    const float* attn = (const float*)d_in[2];
    const float* czw  = (const float*)d_in[3];
    const float* czb  = (const float*)d_in[4];
    // d_in[5], d_in[6] (conv_r_*) and d_in[11], d_in[12] (lin_r_*) are dead code: H0 == 0
    const float* chw  = (const float*)d_in[7];
    const float* chb  = (const float*)d_in[8];
    const float* lzw  = (const float*)d_in[9];
    const float* lzb  = (const float*)d_in[10];
    const float* lhw  = (const float*)d_in[13];
    const float* lhb  = (const float*)d_in[14];
    const float* ow   = (const float*)d_in[15];
    const float* ob   = (const float*)d_in[16];
    float* out = (float*)d_out;

    k_detect<<<1, 256>>>((const unsigned int*)ei);
    k_prep <<<1, 128>>>(attn, czw, czb, chw, chb, lzw, lzb, lhw, lhb);
    k_half <<<(NN * 96 + 255) / 256, 256>>>(x);
    k_clear<<<NB_SCAN, 256>>>();
    k_hist <<<(NE + 255) / 256, 256>>>(ei);
    k_scan1<<<NB_SCAN, 256>>>();
    k_scan2<<<1, 512>>>();
    k_scan3<<<NB_SCAN, 256>>>();
    k_fill <<<(NE + 255) / 256, 256>>>(ei);
    k_spmm <<<(NN + 7) / 8, 256>>>(x);
    k_dense<<<(NN / 8), 128>>>(ow, ob, out);
}